// round 2
// baseline (speedup 1.0000x reference)
#include <cuda_runtime.h>
#include <math.h>

#define NWIN 3200
#define NEG9 -1000000000.0f

// ---------------- static scratch ----------------
__device__ float  d_scal[NWIN*1600];
__device__ float  d_c1  [NWIN*16*1600];
__device__ float  d_p1  [NWIN*16*400];
__device__ float  d_c2  [NWIN*32*400];
__device__ float  d_feat[NWIN*32];
__device__ float  d_emb [NWIN*128];
__device__ float  d_Qm  [NWIN*128];
__device__ float  d_Km  [NWIN*128];
__device__ float  d_attn[16*200*200];
__device__ float  d_adj [16*200*200];
__device__ float  d_dinv[16*200];
__device__ float  d_An  [16*200*200];
__device__ float  d_X1  [NWIN*256];
__device__ float  d_G1  [NWIN*256];
__device__ float  d_X2  [NWIN*256];
__device__ float  d_G2  [NWIN*256];
__device__ float  d_gemb[16*256];
__device__ float  d_gi  [16*768];
__device__ double d_bnsum[96];
__device__ float  d_sc1[16], d_sh1[16], d_sc2[32], d_sh2[32];

__global__ void k_init(float* out){
    int t = threadIdx.x;
    if (t < 96) d_bnsum[t] = 0.0;
    if (t == 96) out[40002] = 0.f;
}

// ---------------- CWT ----------------
__global__ void k_cwt(const float* __restrict__ x, const float* __restrict__ wr,
                      const float* __restrict__ wi){
    __shared__ float xp[100];
    __shared__ float wrs[1600], wis[1600];
    int n = blockIdx.x, tid = threadIdx.x;
    for (int i = tid; i < 100; i += 256){
        int s = i - 24;
        xp[i] = (s >= 0 && s < 50) ? x[n*50 + s] : 0.f;
    }
    for (int i = tid; i < 1600; i += 256){ wrs[i] = wr[i]; wis[i] = wi[i]; }
    __syncthreads();
    for (int idx = tid; idx < 1600; idx += 256){
        int f = idx / 50, j = idx % 50;
        const float* a = &wrs[f*50];
        const float* b = &wis[f*50];
        float re = 0.f, im = 0.f;
        #pragma unroll 10
        for (int k = 0; k < 50; k++){
            float xv = xp[j + k];
            re += xv * a[k];
            im += xv * b[k];
        }
        d_scal[n*1600 + idx] = sqrtf(re*re + im*im);
    }
}

// ---------------- conv1 (1->16) + bias + BN stats ----------------
__global__ void k_conv1(const float* __restrict__ w, const float* __restrict__ b){
    __shared__ float sp[34*52];
    __shared__ float ssum[16], ssq[16];
    int n = blockIdx.x, tid = threadIdx.x;
    int warp = tid >> 5, lane = tid & 31;
    if (tid < 16){ ssum[tid] = 0.f; ssq[tid] = 0.f; }
    for (int i = tid; i < 34*52; i += 256) sp[i] = 0.f;
    __syncthreads();
    const float* in = &d_scal[n*1600];
    for (int i = tid; i < 1600; i += 256){
        int y = i / 50, xx = i % 50;
        sp[(y+1)*52 + (xx+1)] = in[i];
    }
    __syncthreads();
    for (int row = warp; row < 512; row += 8){
        int c = row >> 5, y = row & 31;
        float wl[9];
        #pragma unroll
        for (int k = 0; k < 9; k++) wl[k] = __ldg(&w[c*9 + k]);
        float bias = __ldg(&b[c]);
        float s = 0.f, sq = 0.f;
        float* outp = &d_c1[((n*16 + c)*32 + y)*50];
        #pragma unroll
        for (int half = 0; half < 2; half++){
            int j = lane + half*32;
            if (j < 50){
                float acc = bias;
                #pragma unroll
                for (int dy = 0; dy < 3; dy++){
                    const float* rp = &sp[(y+dy)*52 + j];
                    acc += rp[0]*wl[dy*3] + rp[1]*wl[dy*3+1] + rp[2]*wl[dy*3+2];
                }
                outp[j] = acc;
                s += acc; sq += acc*acc;
            }
        }
        #pragma unroll
        for (int off = 16; off; off >>= 1){
            s  += __shfl_xor_sync(0xffffffffu, s,  off);
            sq += __shfl_xor_sync(0xffffffffu, sq, off);
        }
        if (lane == 0){ atomicAdd(&ssum[c], s); atomicAdd(&ssq[c], sq); }
    }
    __syncthreads();
    if (tid < 16){
        atomicAdd(&d_bnsum[tid],      (double)ssum[tid]);
        atomicAdd(&d_bnsum[16 + tid], (double)ssq[tid]);
    }
}

__global__ void k_bn1fin(const float* __restrict__ g, const float* __restrict__ b){
    int c = threadIdx.x; if (c >= 16) return;
    double cnt = 5120000.0;
    double mu  = d_bnsum[c] / cnt;
    double var = d_bnsum[16 + c] / cnt - mu*mu;
    float sc = g[c] * rsqrtf((float)var + 1e-5f);
    d_sc1[c] = sc;
    d_sh1[c] = b[c] - (float)mu * sc;
}

// ---------------- BN1+relu+pool -> (n,16,16,25) ----------------
__global__ void k_pool1(){
    int idx = blockIdx.x*256 + threadIdx.x;
    if (idx >= NWIN*16*400) return;
    int x = idx % 25, y = (idx/25) & 15, c = (idx/400) & 15, n = idx/6400;
    float sc = d_sc1[c], sh = d_sh1[c];
    const float* p = &d_c1[((n*16+c)*32 + 2*y)*50 + 2*x];
    float v0 = fmaxf(p[0]*sc+sh, 0.f);
    float v1 = fmaxf(p[1]*sc+sh, 0.f);
    float v2 = fmaxf(p[50]*sc+sh, 0.f);
    float v3 = fmaxf(p[51]*sc+sh, 0.f);
    d_p1[idx] = fmaxf(fmaxf(v0,v1), fmaxf(v2,v3));
}

// ---------------- conv2 (16->32) + bias + BN stats ----------------
__global__ void k_conv2(const float* __restrict__ w, const float* __restrict__ b){
    __shared__ float sp[16][18][27];
    __shared__ float ssum[32], ssq[32];
    int n = blockIdx.x, tid = threadIdx.x;
    if (tid < 32){ ssum[tid] = 0.f; ssq[tid] = 0.f; }
    for (int i = tid; i < 16*18*27; i += 256) ((float*)sp)[i] = 0.f;
    __syncthreads();
    const float* in = &d_p1[n*6400];
    for (int i = tid; i < 6400; i += 256){
        int ci = i / 400, y = (i/25) & 15, x = i % 25;
        sp[ci][y+1][x+1] = in[i];
    }
    __syncthreads();
    for (int rr = 0; rr < 2; rr++){
        int row = tid + rr*256;          // row = c*16 + y, 512 rows
        int c = row >> 4, y = row & 15;
        float acc[25];
        float bias = __ldg(&b[c]);
        #pragma unroll
        for (int x = 0; x < 25; x++) acc[x] = bias;
        for (int ci = 0; ci < 16; ci++){
            const float* wp = &w[(c*16 + ci)*9];
            float w0=__ldg(wp),w1=__ldg(wp+1),w2=__ldg(wp+2),w3=__ldg(wp+3),w4=__ldg(wp+4),
                  w5=__ldg(wp+5),w6=__ldg(wp+6),w7=__ldg(wp+7),w8=__ldg(wp+8);
            #pragma unroll
            for (int dy = 0; dy < 3; dy++){
                const float* rp = &sp[ci][y+dy][0];
                float wa = dy==0?w0:(dy==1?w3:w6);
                float wb = dy==0?w1:(dy==1?w4:w7);
                float wc = dy==0?w2:(dy==1?w5:w8);
                float a = rp[0], bb = rp[1];
                #pragma unroll
                for (int x = 0; x < 25; x++){
                    float cc = rp[x+2];
                    acc[x] += a*wa + bb*wb + cc*wc;
                    a = bb; bb = cc;
                }
            }
        }
        float s = 0.f, sq = 0.f;
        float* outp = &d_c2[((n*32 + c)*16 + y)*25];
        #pragma unroll
        for (int x = 0; x < 25; x++){
            outp[x] = acc[x];
            s += acc[x]; sq += acc[x]*acc[x];
        }
        atomicAdd(&ssum[c], s); atomicAdd(&ssq[c], sq);
    }
    __syncthreads();
    if (tid < 32){
        atomicAdd(&d_bnsum[32 + tid], (double)ssum[tid]);
        atomicAdd(&d_bnsum[64 + tid], (double)ssq[tid]);
    }
}

__global__ void k_bn2fin(const float* __restrict__ g, const float* __restrict__ b){
    int c = threadIdx.x; if (c >= 32) return;
    double cnt = 1280000.0;
    double mu  = d_bnsum[32 + c] / cnt;
    double var = d_bnsum[64 + c] / cnt - mu*mu;
    float sc = g[c] * rsqrtf((float)var + 1e-5f);
    d_sc2[c] = sc;
    d_sh2[c] = b[c] - (float)mu * sc;
}

// ---------------- BN2+relu+pool(8x12)+spatial mean -> feat (n,32) ----------------
__global__ void k_pool2feat(){
    __shared__ float cs[32];
    int n = blockIdx.x, tid = threadIdx.x;
    if (tid < 32) cs[tid] = 0.f;
    __syncthreads();
    for (int idx = tid; idx < 3072; idx += 256){
        int x = idx % 12, y = (idx/12) & 7, c = idx/96;
        float sc = d_sc2[c], sh = d_sh2[c];
        const float* p = &d_c2[((n*32+c)*16 + 2*y)*25 + 2*x];
        float v0 = fmaxf(p[0]*sc+sh, 0.f);
        float v1 = fmaxf(p[1]*sc+sh, 0.f);
        float v2 = fmaxf(p[25]*sc+sh, 0.f);
        float v3 = fmaxf(p[26]*sc+sh, 0.f);
        atomicAdd(&cs[c], fmaxf(fmaxf(v0,v1), fmaxf(v2,v3)));
    }
    __syncthreads();
    if (tid < 32) d_feat[n*32 + tid] = cs[tid] * (1.f/96.f);
}

// ---------------- generic tiled SGEMM: C = act(scale*A@B(+T) + bias) ----------------
template<int ACT, bool TRANSB>
__global__ void k_gemm(const float* __restrict__ A, const float* __restrict__ B,
                       const float* __restrict__ bias, float* __restrict__ C,
                       int M, int N, int Kd, int sA, int sB, int sC, float scale){
    __shared__ float As[16][65];
    __shared__ float Bs[16][65];
    int bz = blockIdx.z;
    A += (long)bz*sA; B += (long)bz*sB; C += (long)bz*sC;
    int tid = threadIdx.x;
    int tx = tid & 15, ty = tid >> 4;
    int row0 = blockIdx.y*64, col0 = blockIdx.x*64;
    float acc[4][4] = {};
    for (int k0 = 0; k0 < Kd; k0 += 16){
        #pragma unroll
        for (int l = 0; l < 4; l++){
            int idx = tid + l*256;
            int m = idx >> 4, k = idx & 15;
            int gm = row0 + m, gk = k0 + k;
            As[k][m] = (gm < M && gk < Kd) ? A[gm*Kd + gk] : 0.f;
        }
        #pragma unroll
        for (int l = 0; l < 4; l++){
            int idx = tid + l*256;
            if (TRANSB){
                int nn = idx >> 4, k = idx & 15;
                int gn = col0 + nn, gk = k0 + k;
                Bs[k][nn] = (gn < N && gk < Kd) ? B[gn*Kd + gk] : 0.f;
            } else {
                int k = idx >> 6, nn = idx & 63;
                int gn = col0 + nn, gk = k0 + k;
                Bs[k][nn] = (gn < N && gk < Kd) ? B[gk*N + gn] : 0.f;
            }
        }
        __syncthreads();
        #pragma unroll
        for (int k = 0; k < 16; k++){
            float a[4], bb[4];
            #pragma unroll
            for (int i = 0; i < 4; i++) a[i] = As[k][ty*4+i];
            #pragma unroll
            for (int j = 0; j < 4; j++) bb[j] = Bs[k][tx*4+j];
            #pragma unroll
            for (int i = 0; i < 4; i++)
                #pragma unroll
                for (int j = 0; j < 4; j++)
                    acc[i][j] += a[i]*bb[j];
        }
        __syncthreads();
    }
    #pragma unroll
    for (int i = 0; i < 4; i++){
        int gm = row0 + ty*4 + i;
        if (gm >= M) continue;
        #pragma unroll
        for (int j = 0; j < 4; j++){
            int gn = col0 + tx*4 + j;
            if (gn >= N) continue;
            float v = acc[i][j]*scale;
            if (bias) v += bias[gn];
            if (ACT == 1) v = fmaxf(v, 0.f);
            if (ACT == 2) v = v > 0.f ? v : 0.2f*v;
            C[gm*N + gn] = v;
        }
    }
}

// ---------------- top-K(20) mask + softmax per (t,r) row ----------------
__global__ void k_adj(){
    __shared__ float sa[200];
    __shared__ float red[256];
    int b = blockIdx.x, tid = threadIdx.x;
    int t = b / 200, r = b % 200;
    const float* row = &d_attn[(t*200 + r)*200];
    if (tid < 200) sa[tid] = row[tid];
    __syncthreads();
    float v = NEG9;
    if (tid < 200){
        float my = sa[tid];
        int cnt = 0;
        for (int j = 0; j < 200; j++){
            float aj = sa[j];
            cnt += (aj > my) || (aj == my && j < tid);
        }
        if (cnt < 20) v = (my == 0.f) ? NEG9 : my;
    }
    red[tid] = (tid < 200) ? v : NEG9;
    __syncthreads();
    for (int off = 128; off; off >>= 1){
        if (tid < off) red[tid] = fmaxf(red[tid], red[tid + off]);
        __syncthreads();
    }
    float m = red[0];
    __syncthreads();
    float e = (tid < 200) ? expf(v - m) : 0.f;
    red[tid] = e;
    __syncthreads();
    for (int off = 128; off; off >>= 1){
        if (tid < off) red[tid] += red[tid + off];
        __syncthreads();
    }
    float s = red[0];
    if (tid < 200) d_adj[(t*200 + r)*200 + tid] = e / s;
}

// ---------------- degree + dinv (column sums of adj with self-loop) ----------------
__global__ void k_deg(){
    int t = blockIdx.x, s = threadIdx.x;
    if (s >= 200) return;
    const float* a = &d_adj[t*40000];
    float col = 0.f;
    for (int r = 0; r < 200; r++) col += a[r*200 + s];
    float diag = a[s*200 + s];
    float dsl = (diag == 0.f) ? 1.f : diag;
    float deg = col - diag + dsl;
    deg = (deg > 0.f) ? deg : 1.f;
    d_dinv[t*200 + s] = rsqrtf(deg);
}

// ---------------- An[t,r,s] = dinv[r]*adj_sl[t,s,r]*dinv[s] ----------------
__global__ void k_An(){
    int idx = blockIdx.x*256 + threadIdx.x;
    if (idx >= 640000) return;
    int s = idx % 200, r = (idx/200) % 200, t = idx/40000;
    const float* a = &d_adj[t*40000];
    float val;
    if (r == s){
        float diag = a[r*200 + r];
        val = (diag == 0.f) ? 1.f : diag;
    } else {
        val = a[s*200 + r];
    }
    d_An[idx] = d_dinv[t*200 + r] * val * d_dinv[t*200 + s];
}

// ---------------- g_emb = mean over r ----------------
__global__ void k_gemb(){
    int t = blockIdx.x, h = threadIdx.x;
    float s = 0.f;
    for (int r = 0; r < 200; r++) s += d_G2[(t*200 + r)*256 + h];
    d_gemb[t*256 + h] = s * (1.f/200.f);
}

// ---------------- GRU: 16 sequential steps, single block ----------------
__global__ void k_gru(const float* __restrict__ whh, const float* __restrict__ bhh,
                      const float* __restrict__ clsw, const float* __restrict__ clsb,
                      float* out){
    __shared__ float hs[256];
    int i = threadIdx.x;
    hs[i] = 0.f;
    __syncthreads();
    float b0 = bhh[i], b1 = bhh[256+i], b2 = bhh[512+i];
    const float4* w0 = (const float4*)(whh + i*256);
    const float4* w1 = (const float4*)(whh + (256+i)*256);
    const float4* w2 = (const float4*)(whh + (512+i)*256);
    for (int t = 0; t < 16; t++){
        const float4* hv = (const float4*)hs;
        float hr = b0, hz = b1, hn = b2;
        #pragma unroll 8
        for (int k = 0; k < 64; k++){
            float4 h4 = hv[k];
            float4 a = __ldg(&w0[k]);
            float4 b = __ldg(&w1[k]);
            float4 c = __ldg(&w2[k]);
            hr += a.x*h4.x + a.y*h4.y + a.z*h4.z + a.w*h4.w;
            hz += b.x*h4.x + b.y*h4.y + b.z*h4.z + b.w*h4.w;
            hn += c.x*h4.x + c.y*h4.y + c.z*h4.z + c.w*h4.w;
        }
        float gir = d_gi[t*768 + i], giz = d_gi[t*768 + 256 + i], gin = d_gi[t*768 + 512 + i];
        float rr = 1.f / (1.f + expf(-(gir + hr)));
        float z  = 1.f / (1.f + expf(-(giz + hz)));
        float nn = tanhf(gin + rr*hn);
        float hnew = (1.f - z)*nn + z*hs[i];
        __syncthreads();
        hs[i] = hnew;
        __syncthreads();
    }
    if (i < 2){
        float s = clsb[i];
        for (int k = 0; k < 256; k++) s += clsw[i*256 + k]*hs[k];
        out[i] = s;
    }
}

// ---------------- avg_adj + edge variance (ddof=1) ----------------
__global__ void k_avgvar(float* out){
    __shared__ float red[256];
    int idx = blockIdx.x*256 + threadIdx.x;
    float var = 0.f;
    if (idx < 40000){
        float x[16];
        float s = 0.f;
        #pragma unroll
        for (int t = 0; t < 16; t++){ x[t] = d_adj[t*40000 + idx]; s += x[t]; }
        float mu = s * (1.f/16.f);
        float ssd = 0.f;
        #pragma unroll
        for (int t = 0; t < 16; t++){ float d = x[t] - mu; ssd += d*d; }
        var = ssd * (1.f/15.f);
        out[2 + idx] = mu;
    }
    red[threadIdx.x] = var;
    __syncthreads();
    for (int off = 128; off; off >>= 1){
        if (threadIdx.x < off) red[threadIdx.x] += red[threadIdx.x + off];
        __syncthreads();
    }
    if (threadIdx.x == 0) atomicAdd(&out[40002], red[0] * (1.f/40000.f));
}

// ---------------- driver ----------------
extern "C" void kernel_launch(void* const* d_in, const int* in_sizes, int n_in,
                              void* d_out, int out_size){
    const float* tw     = (const float*)d_in[0];
    const float* wavr   = (const float*)d_in[1];
    const float* wavi   = (const float*)d_in[2];
    const float* c1w    = (const float*)d_in[3];
    const float* c1b    = (const float*)d_in[4];
    const float* bn1g   = (const float*)d_in[5];
    const float* bn1b   = (const float*)d_in[6];
    const float* c2w    = (const float*)d_in[7];
    const float* c2b    = (const float*)d_in[8];
    const float* bn2g   = (const float*)d_in[9];
    const float* bn2b   = (const float*)d_in[10];
    const float* fcw    = (const float*)d_in[11];
    const float* fcb    = (const float*)d_in[12];
    const float* qw     = (const float*)d_in[13];
    const float* qb     = (const float*)d_in[14];
    const float* kw     = (const float*)d_in[15];
    const float* kb     = (const float*)d_in[16];
    const float* g1w    = (const float*)d_in[17];
    const float* g1b    = (const float*)d_in[18];
    const float* g2w    = (const float*)d_in[19];
    const float* g2b    = (const float*)d_in[20];
    const float* wih    = (const float*)d_in[21];
    const float* whh    = (const float*)d_in[22];
    const float* bih    = (const float*)d_in[23];
    const float* bhh    = (const float*)d_in[24];
    const float* clsw   = (const float*)d_in[25];
    const float* clsb   = (const float*)d_in[26];
    float* out = (float*)d_out;

    float *p_emb, *p_Q, *p_K, *p_attn, *p_An, *p_X1, *p_G1, *p_X2, *p_G2, *p_feat, *p_gemb, *p_gi;
    cudaGetSymbolAddress((void**)&p_emb,  d_emb);
    cudaGetSymbolAddress((void**)&p_Q,    d_Qm);
    cudaGetSymbolAddress((void**)&p_K,    d_Km);
    cudaGetSymbolAddress((void**)&p_attn, d_attn);
    cudaGetSymbolAddress((void**)&p_An,   d_An);
    cudaGetSymbolAddress((void**)&p_X1,   d_X1);
    cudaGetSymbolAddress((void**)&p_G1,   d_G1);
    cudaGetSymbolAddress((void**)&p_X2,   d_X2);
    cudaGetSymbolAddress((void**)&p_G2,   d_G2);
    cudaGetSymbolAddress((void**)&p_feat, d_feat);
    cudaGetSymbolAddress((void**)&p_gemb, d_gemb);
    cudaGetSymbolAddress((void**)&p_gi,   d_gi);

    k_init<<<1, 128>>>(out);
    k_cwt<<<NWIN, 256>>>(tw, wavr, wavi);
    k_conv1<<<NWIN, 256>>>(c1w, c1b);
    k_bn1fin<<<1, 16>>>(bn1g, bn1b);
    k_pool1<<<(NWIN*16*400 + 255)/256, 256>>>();
    k_conv2<<<NWIN, 256>>>(c2w, c2b);
    k_bn2fin<<<1, 32>>>(bn2g, bn2b);
    k_pool2feat<<<NWIN, 256>>>();

    // emb = feat @ fcw^T + fcb
    k_gemm<0, true><<<dim3(2, 50, 1), 256>>>(p_feat, fcw, fcb, p_emb, 3200, 128, 32, 0, 0, 0, 1.f);
    // Q, K
    k_gemm<0, true><<<dim3(2, 50, 1), 256>>>(p_emb, qw, qb, p_Q, 3200, 128, 128, 0, 0, 0, 1.f);
    k_gemm<0, true><<<dim3(2, 50, 1), 256>>>(p_emb, kw, kb, p_K, 3200, 128, 128, 0, 0, 0, 1.f);
    // attn = leaky(Q K^T / sqrt(E)), batched over t
    k_gemm<2, true><<<dim3(4, 4, 16), 256>>>(p_Q, p_K, nullptr, p_attn,
                                             200, 200, 128, 25600, 25600, 40000, 0.08838834764831845f);
    k_adj<<<3200, 256>>>();
    k_deg<<<16, 256>>>();
    k_An<<<2500, 256>>>();
    // X1 = emb @ gcn1_w ; G1 = relu(An @ X1 + b1)
    k_gemm<0, false><<<dim3(4, 50, 1), 256>>>(p_emb, g1w, nullptr, p_X1, 3200, 256, 128, 0, 0, 0, 1.f);
    k_gemm<1, false><<<dim3(4, 4, 16), 256>>>(p_An, p_X1, g1b, p_G1, 200, 256, 200, 40000, 51200, 51200, 1.f);
    // X2 = G1 @ gcn2_w ; G2 = relu(An @ X2 + b2)
    k_gemm<0, false><<<dim3(4, 50, 1), 256>>>(p_G1, g2w, nullptr, p_X2, 3200, 256, 256, 0, 0, 0, 1.f);
    k_gemm<1, false><<<dim3(4, 4, 16), 256>>>(p_An, p_X2, g2b, p_G2, 200, 256, 200, 40000, 51200, 51200, 1.f);
    k_gemb<<<16, 256>>>();
    // gi = g_emb @ wih^T + bih
    k_gemm<0, true><<<dim3(12, 1, 1), 256>>>(p_gemb, wih, bih, p_gi, 16, 768, 256, 0, 0, 0, 1.f);
    k_gru<<<1, 256>>>(whh, bhh, clsw, clsb, out);
    k_avgvar<<<157, 256>>>(out);
}

// round 4
// speedup vs baseline: 1.3688x; 1.3688x over previous
#include <cuda_runtime.h>
#include <math.h>

#define NWIN 3200
#define NEG9 -1000000000.0f

// ---------------- static scratch ----------------
__device__ float  d_c1max[NWIN*16*16*25];
__device__ float  d_c1min[NWIN*16*16*25];
__device__ float  d_c2max[NWIN*32*8*12];
__device__ float  d_c2min[NWIN*32*8*12];
__device__ float  d_feat[NWIN*32];
__device__ float  d_emb [NWIN*128];
__device__ float  d_Qm  [NWIN*128];
__device__ float  d_Km  [NWIN*128];
__device__ float  d_attn[16*200*200];
__device__ float  d_adj [16*200*200];
__device__ float  d_dinv[16*200];
__device__ float  d_An  [16*200*200];
__device__ float  d_X1  [NWIN*256];
__device__ float  d_G1  [NWIN*256];
__device__ float  d_X2  [NWIN*256];
__device__ float  d_G2  [NWIN*256];
__device__ float  d_gemb[16*256];
__device__ float  d_gi  [16*768];
__device__ double d_bnsum[96];
__device__ float  d_sc1[16], d_sh1[16], d_sc2[32], d_sh2[32];

__global__ void k_init(float* out){
    int t = threadIdx.x;
    if (t < 96) d_bnsum[t] = 0.0;
    if (t == 96) out[40002] = 0.f;
}

// ---------------- fused CWT + conv1(1->16) + BN stats + raw 2x2 max/min pool ----------------
__global__ void __launch_bounds__(256) k_cwtconv1(
        const float* __restrict__ x, const float* __restrict__ wr,
        const float* __restrict__ wi, const float* __restrict__ w,
        const float* __restrict__ b){
    __shared__ float xp[112];
    __shared__ float wrs[1600], wis[1600];
    __shared__ float sp[34*52];
    __shared__ float ssum[16], ssq[16];
    int n = blockIdx.x, tid = threadIdx.x;
    if (tid < 16){ ssum[tid] = 0.f; ssq[tid] = 0.f; }
    for (int i = tid; i < 112; i += 256){
        int s = i - 24;
        xp[i] = (s >= 0 && s < 50) ? x[n*50 + s] : 0.f;
    }
    for (int i = tid; i < 1600; i += 256){ wrs[i] = wr[i]; wis[i] = wi[i]; }
    for (int i = tid; i < 34*52; i += 256) sp[i] = 0.f;
    __syncthreads();

    // ---- CWT: 7 consecutive outputs per thread, sliding register window ----
    {
        int f = tid >> 3, jb = (tid & 7) * 7;
        const float* a  = &wrs[f*50];
        const float* bb = &wis[f*50];
        float re[7] = {0,0,0,0,0,0,0}, im[7] = {0,0,0,0,0,0,0};
        float win[7];
        #pragma unroll
        for (int q = 0; q < 7; q++) win[q] = xp[jb + q];
        #pragma unroll
        for (int k = 0; k < 50; k++){
            float wa = a[k], wb = bb[k];
            #pragma unroll
            for (int q = 0; q < 7; q++){ re[q] += win[q]*wa; im[q] += win[q]*wb; }
            #pragma unroll
            for (int q = 0; q < 6; q++) win[q] = win[q+1];
            win[6] = xp[jb + k + 7];
        }
        #pragma unroll
        for (int q = 0; q < 7; q++){
            int j = jb + q;
            if (j < 50) sp[(f+1)*52 + (j+1)] = sqrtf(re[q]*re[q] + im[q]*im[q]);
        }
    }
    __syncthreads();

    // ---- conv1: thread = (c, ypair); 2 output rows, sliding 4-row window ----
    int c = tid >> 4, yp = tid & 15;
    float wl[9];
    #pragma unroll
    for (int k = 0; k < 9; k++) wl[k] = __ldg(&w[c*9 + k]);
    float bias = __ldg(&b[c]);
    const float* r0 = &sp[(2*yp + 0)*52];
    const float* r1 = &sp[(2*yp + 1)*52];
    const float* r2 = &sp[(2*yp + 2)*52];
    const float* r3 = &sp[(2*yp + 3)*52];
    float a0=r0[0], b0=r0[1], a1=r1[0], b1=r1[1];
    float a2=r2[0], b2=r2[1], a3=r3[0], b3=r3[1];
    float s = 0.f, sq = 0.f, pm = 0.f, pn = 0.f;
    float* omax = &d_c1max[((n*16 + c)*16 + yp)*25];
    float* omin = &d_c1min[((n*16 + c)*16 + yp)*25];
    #pragma unroll
    for (int xx = 0; xx < 50; xx++){
        float c0=r0[xx+2], c1=r1[xx+2], c2=r2[xx+2], c3=r3[xx+2];
        float o0 = bias + a0*wl[0]+b0*wl[1]+c0*wl[2]
                        + a1*wl[3]+b1*wl[4]+c1*wl[5]
                        + a2*wl[6]+b2*wl[7]+c2*wl[8];
        float o1 = bias + a1*wl[0]+b1*wl[1]+c1*wl[2]
                        + a2*wl[3]+b2*wl[4]+c2*wl[5]
                        + a3*wl[6]+b3*wl[7]+c3*wl[8];
        s += o0 + o1; sq += o0*o0 + o1*o1;
        float mx = fmaxf(o0,o1), mn = fminf(o0,o1);
        if ((xx & 1) == 0){ pm = mx; pn = mn; }
        else { omax[xx>>1] = fmaxf(pm, mx); omin[xx>>1] = fminf(pn, mn); }
        a0=b0; b0=c0; a1=b1; b1=c1; a2=b2; b2=c2; a3=b3; b3=c3;
    }
    atomicAdd(&ssum[c], s); atomicAdd(&ssq[c], sq);
    __syncthreads();
    if (tid < 16){
        atomicAdd(&d_bnsum[tid],      (double)ssum[tid]);
        atomicAdd(&d_bnsum[16 + tid], (double)ssq[tid]);
    }
}

__global__ void k_bn1fin(const float* __restrict__ g, const float* __restrict__ b){
    int c = threadIdx.x; if (c >= 16) return;
    double cnt = 5120000.0;
    double mu  = d_bnsum[c] / cnt;
    double var = d_bnsum[16 + c] / cnt - mu*mu;
    float sc = g[c] * rsqrtf((float)var + 1e-5f);
    d_sc1[c] = sc;
    d_sh1[c] = b[c] - (float)mu * sc;
}

// ---------------- conv2 (16->32): BN1+relu on load, conv, BN stats, raw pool ----------------
__global__ void __launch_bounds__(256) k_conv2(const float* __restrict__ w,
                                               const float* __restrict__ b){
    __shared__ float sp[16*486];     // 16 x 18 x 27, 31104 B
    __shared__ float ssum[32], ssq[32];
    int n = blockIdx.x, tid = threadIdx.x;
    if (tid < 32){ ssum[tid] = 0.f; ssq[tid] = 0.f; }
    for (int i = tid; i < 16*486; i += 256) sp[i] = 0.f;
    __syncthreads();
    for (int i = tid; i < 6400; i += 256){
        int ci = i / 400, rem = i % 400, y = rem / 25, xx = rem % 25;
        float sc = d_sc1[ci], sh = d_sh1[ci];
        float mx = d_c1max[n*6400 + i], mn = d_c1min[n*6400 + i];
        float v = fmaxf(sc * (sc >= 0.f ? mx : mn) + sh, 0.f);
        sp[ci*486 + (y+1)*27 + (xx+1)] = v;
    }
    __syncthreads();

    int c = tid >> 3, yp = tid & 7;
    float bias = __ldg(&b[c]);
    float acc0[25], acc1[25];
    #pragma unroll
    for (int xx = 0; xx < 25; xx++){ acc0[xx] = bias; acc1[xx] = bias; }
    for (int ci = 0; ci < 16; ci++){
        const float* wp = &w[(c*16 + ci)*9];
        float w0=__ldg(wp+0),w1=__ldg(wp+1),w2=__ldg(wp+2),
              w3=__ldg(wp+3),w4=__ldg(wp+4),w5=__ldg(wp+5),
              w6=__ldg(wp+6),w7=__ldg(wp+7),w8=__ldg(wp+8);
        const float* r0 = &sp[ci*486 + (2*yp + 0)*27];
        const float* r1 = &sp[ci*486 + (2*yp + 1)*27];
        const float* r2 = &sp[ci*486 + (2*yp + 2)*27];
        const float* r3 = &sp[ci*486 + (2*yp + 3)*27];
        float a0=r0[0], b0=r0[1], a1=r1[0], b1=r1[1];
        float a2=r2[0], b2=r2[1], a3=r3[0], b3=r3[1];
        #pragma unroll
        for (int xx = 0; xx < 25; xx++){
            float c0=r0[xx+2], c1=r1[xx+2], c2=r2[xx+2], c3=r3[xx+2];
            acc0[xx] += a0*w0+b0*w1+c0*w2 + a1*w3+b1*w4+c1*w5 + a2*w6+b2*w7+c2*w8;
            acc1[xx] += a1*w0+b1*w1+c1*w2 + a2*w3+b2*w4+c2*w5 + a3*w6+b3*w7+c3*w8;
            a0=b0; b0=c0; a1=b1; b1=c1; a2=b2; b2=c2; a3=b3; b3=c3;
        }
    }
    float s = 0.f, sq = 0.f;
    #pragma unroll
    for (int xx = 0; xx < 25; xx++){
        s  += acc0[xx] + acc1[xx];
        sq += acc0[xx]*acc0[xx] + acc1[xx]*acc1[xx];
    }
    float* omax = &d_c2max[((n*32 + c)*8 + yp)*12];
    float* omin = &d_c2min[((n*32 + c)*8 + yp)*12];
    #pragma unroll
    for (int xq = 0; xq < 12; xq++){
        float m0 = fmaxf(acc0[2*xq], acc0[2*xq+1]);
        float m1 = fmaxf(acc1[2*xq], acc1[2*xq+1]);
        omax[xq] = fmaxf(m0, m1);
        float n0 = fminf(acc0[2*xq], acc0[2*xq+1]);
        float n1 = fminf(acc1[2*xq], acc1[2*xq+1]);
        omin[xq] = fminf(n0, n1);
    }
    atomicAdd(&ssum[c], s); atomicAdd(&ssq[c], sq);
    __syncthreads();
    if (tid < 32){
        atomicAdd(&d_bnsum[32 + tid], (double)ssum[tid]);
        atomicAdd(&d_bnsum[64 + tid], (double)ssq[tid]);
    }
}

__global__ void k_bn2fin(const float* __restrict__ g, const float* __restrict__ b){
    int c = threadIdx.x; if (c >= 32) return;
    double cnt = 1280000.0;
    double mu  = d_bnsum[32 + c] / cnt;
    double var = d_bnsum[64 + c] / cnt - mu*mu;
    float sc = g[c] * rsqrtf((float)var + 1e-5f);
    d_sc2[c] = sc;
    d_sh2[c] = b[c] - (float)mu * sc;
}

// ---------------- feat: BN2+relu on pooled, spatial mean -> (n,32) ----------------
__global__ void k_feat(){
    __shared__ float red[256];
    int n = blockIdx.x, tid = threadIdx.x;
    int c = tid & 31, yp = tid >> 5;
    float sc = d_sc2[c], sh = d_sh2[c];
    const float* pmax = &d_c2max[((n*32 + c)*8 + yp)*12];
    const float* pmin = &d_c2min[((n*32 + c)*8 + yp)*12];
    float s = 0.f;
    #pragma unroll
    for (int xq = 0; xq < 12; xq++){
        float v = sc >= 0.f ? pmax[xq] : pmin[xq];
        s += fmaxf(sc*v + sh, 0.f);
    }
    red[tid] = s;
    __syncthreads();
    if (tid < 32){
        float t = 0.f;
        #pragma unroll
        for (int q = 0; q < 8; q++) t += red[q*32 + tid];
        d_feat[n*32 + tid] = t * (1.f/96.f);
    }
}

// ---------------- generic tiled SGEMM (64x64x16, 4x4 micro, float4 smem reads) ----------------
template<int ACT, bool TRANSB>
__global__ void __launch_bounds__(256) k_gemm(
        const float* __restrict__ A, const float* __restrict__ B,
        const float* __restrict__ bias, float* __restrict__ C,
        int M, int N, int Kd, int sA, int sB, int sC, float scale){
    __shared__ float As[16][68];
    __shared__ float Bs[16][68];
    int bz = blockIdx.z;
    A += (long)bz*sA; B += (long)bz*sB; C += (long)bz*sC;
    int tid = threadIdx.x;
    int tx = tid & 15, ty = tid >> 4;
    int row0 = blockIdx.y*64, col0 = blockIdx.x*64;
    float acc[4][4] = {};
    for (int k0 = 0; k0 < Kd; k0 += 16){
        #pragma unroll
        for (int l = 0; l < 4; l++){
            int idx = tid + l*256;
            int m = idx >> 4, k = idx & 15;
            int gm = row0 + m, gk = k0 + k;
            As[k][m] = (gm < M && gk < Kd) ? A[gm*Kd + gk] : 0.f;
        }
        #pragma unroll
        for (int l = 0; l < 4; l++){
            int idx = tid + l*256;
            if (TRANSB){
                int nn = idx >> 4, k = idx & 15;
                int gn = col0 + nn, gk = k0 + k;
                Bs[k][nn] = (gn < N && gk < Kd) ? B[gn*Kd + gk] : 0.f;
            } else {
                int k = idx >> 6, nn = idx & 63;
                int gn = col0 + nn, gk = k0 + k;
                Bs[k][nn] = (gn < N && gk < Kd) ? B[gk*N + gn] : 0.f;
            }
        }
        __syncthreads();
        #pragma unroll
        for (int k = 0; k < 16; k++){
            float4 av = *reinterpret_cast<const float4*>(&As[k][ty*4]);
            float4 bv = *reinterpret_cast<const float4*>(&Bs[k][tx*4]);
            float a[4] = {av.x, av.y, av.z, av.w};
            float bb[4] = {bv.x, bv.y, bv.z, bv.w};
            #pragma unroll
            for (int i = 0; i < 4; i++)
                #pragma unroll
                for (int j = 0; j < 4; j++)
                    acc[i][j] += a[i]*bb[j];
        }
        __syncthreads();
    }
    #pragma unroll
    for (int i = 0; i < 4; i++){
        int gm = row0 + ty*4 + i;
        if (gm >= M) continue;
        #pragma unroll
        for (int j = 0; j < 4; j++){
            int gn = col0 + tx*4 + j;
            if (gn >= N) continue;
            float v = acc[i][j]*scale;
            if (bias) v += bias[gn];
            if (ACT == 1) v = fmaxf(v, 0.f);
            if (ACT == 2) v = v > 0.f ? v : 0.2f*v;
            C[gm*N + gn] = v;
        }
    }
}

// ---------------- top-K(20) mask + softmax per (t,r) row ----------------
__global__ void k_adj(){
    __shared__ float sa[200];
    __shared__ float red[256];
    int b = blockIdx.x, tid = threadIdx.x;
    int t = b / 200, r = b % 200;
    const float* row = &d_attn[(t*200 + r)*200];
    if (tid < 200) sa[tid] = row[tid];
    __syncthreads();
    float v = NEG9;
    if (tid < 200){
        float my = sa[tid];
        int cnt = 0;
        for (int j = 0; j < 200; j++){
            float aj = sa[j];
            cnt += (aj > my) || (aj == my && j < tid);
        }
        if (cnt < 20) v = (my == 0.f) ? NEG9 : my;
    }
    red[tid] = (tid < 200) ? v : NEG9;
    __syncthreads();
    for (int off = 128; off; off >>= 1){
        if (tid < off) red[tid] = fmaxf(red[tid], red[tid + off]);
        __syncthreads();
    }
    float m = red[0];
    __syncthreads();
    float e = (tid < 200) ? expf(v - m) : 0.f;
    red[tid] = e;
    __syncthreads();
    for (int off = 128; off; off >>= 1){
        if (tid < off) red[tid] += red[tid + off];
        __syncthreads();
    }
    float s = red[0];
    if (tid < 200) d_adj[(t*200 + r)*200 + tid] = e / s;
}

// ---------------- degree + dinv ----------------
__global__ void k_deg(){
    int t = blockIdx.x, s = threadIdx.x;
    if (s >= 200) return;
    const float* a = &d_adj[t*40000];
    float col = 0.f;
    for (int r = 0; r < 200; r++) col += a[r*200 + s];
    float diag = a[s*200 + s];
    float dsl = (diag == 0.f) ? 1.f : diag;
    float deg = col - diag + dsl;
    deg = (deg > 0.f) ? deg : 1.f;
    d_dinv[t*200 + s] = rsqrtf(deg);
}

// ---------------- An[t,r,s] = dinv[r]*adj_sl[t,s,r]*dinv[s] ----------------
__global__ void k_An(){
    int idx = blockIdx.x*256 + threadIdx.x;
    if (idx >= 640000) return;
    int s = idx % 200, r = (idx/200) % 200, t = idx/40000;
    const float* a = &d_adj[t*40000];
    float val;
    if (r == s){
        float diag = a[r*200 + r];
        val = (diag == 0.f) ? 1.f : diag;
    } else {
        val = a[s*200 + r];
    }
    d_An[idx] = d_dinv[t*200 + r] * val * d_dinv[t*200 + s];
}

// ---------------- g_emb = mean over r ----------------
__global__ void k_gemb(){
    int t = blockIdx.x, h = threadIdx.x;
    float s = 0.f;
    for (int r = 0; r < 200; r++) s += d_G2[(t*200 + r)*256 + h];
    d_gemb[t*256 + h] = s * (1.f/200.f);
}

// ---------------- GRU ----------------
__global__ void k_gru(const float* __restrict__ whh, const float* __restrict__ bhh,
                      const float* __restrict__ clsw, const float* __restrict__ clsb,
                      float* out){
    __shared__ float hs[256];
    int i = threadIdx.x;
    hs[i] = 0.f;
    __syncthreads();
    float b0 = bhh[i], b1 = bhh[256+i], b2 = bhh[512+i];
    const float4* w0 = (const float4*)(whh + i*256);
    const float4* w1 = (const float4*)(whh + (256+i)*256);
    const float4* w2 = (const float4*)(whh + (512+i)*256);
    for (int t = 0; t < 16; t++){
        const float4* hv = (const float4*)hs;
        float hr = b0, hz = b1, hn = b2;
        #pragma unroll 8
        for (int k = 0; k < 64; k++){
            float4 h4 = hv[k];
            float4 a = __ldg(&w0[k]);
            float4 b = __ldg(&w1[k]);
            float4 c = __ldg(&w2[k]);
            hr += a.x*h4.x + a.y*h4.y + a.z*h4.z + a.w*h4.w;
            hz += b.x*h4.x + b.y*h4.y + b.z*h4.z + b.w*h4.w;
            hn += c.x*h4.x + c.y*h4.y + c.z*h4.z + c.w*h4.w;
        }
        float gir = d_gi[t*768 + i], giz = d_gi[t*768 + 256 + i], gin = d_gi[t*768 + 512 + i];
        float rr = 1.f / (1.f + expf(-(gir + hr)));
        float z  = 1.f / (1.f + expf(-(giz + hz)));
        float nn = tanhf(gin + rr*hn);
        float hnew = (1.f - z)*nn + z*hs[i];
        __syncthreads();
        hs[i] = hnew;
        __syncthreads();
    }
    if (i < 2){
        float s = clsb[i];
        for (int k = 0; k < 256; k++) s += clsw[i*256 + k]*hs[k];
        out[i] = s;
    }
}

// ---------------- avg_adj + edge variance ----------------
__global__ void k_avgvar(float* out){
    __shared__ float red[256];
    int idx = blockIdx.x*256 + threadIdx.x;
    float var = 0.f;
    if (idx < 40000){
        float x[16];
        float s = 0.f;
        #pragma unroll
        for (int t = 0; t < 16; t++){ x[t] = d_adj[t*40000 + idx]; s += x[t]; }
        float mu = s * (1.f/16.f);
        float ssd = 0.f;
        #pragma unroll
        for (int t = 0; t < 16; t++){ float d = x[t] - mu; ssd += d*d; }
        var = ssd * (1.f/15.f);
        out[2 + idx] = mu;
    }
    red[threadIdx.x] = var;
    __syncthreads();
    for (int off = 128; off; off >>= 1){
        if (threadIdx.x < off) red[threadIdx.x] += red[threadIdx.x + off];
        __syncthreads();
    }
    if (threadIdx.x == 0) atomicAdd(&out[40002], red[0] * (1.f/40000.f));
}

// ---------------- driver ----------------
extern "C" void kernel_launch(void* const* d_in, const int* in_sizes, int n_in,
                              void* d_out, int out_size){
    const float* tw   = (const float*)d_in[0];
    const float* wavr = (const float*)d_in[1];
    const float* wavi = (const float*)d_in[2];
    const float* c1w  = (const float*)d_in[3];
    const float* c1b  = (const float*)d_in[4];
    const float* bn1g = (const float*)d_in[5];
    const float* bn1b = (const float*)d_in[6];
    const float* c2w  = (const float*)d_in[7];
    const float* c2b  = (const float*)d_in[8];
    const float* bn2g = (const float*)d_in[9];
    const float* bn2b = (const float*)d_in[10];
    const float* fcw  = (const float*)d_in[11];
    const float* fcb  = (const float*)d_in[12];
    const float* qw   = (const float*)d_in[13];
    const float* qb   = (const float*)d_in[14];
    const float* kw   = (const float*)d_in[15];
    const float* kb   = (const float*)d_in[16];
    const float* g1w  = (const float*)d_in[17];
    const float* g1b  = (const float*)d_in[18];
    const float* g2w  = (const float*)d_in[19];
    const float* g2b  = (const float*)d_in[20];
    const float* wih  = (const float*)d_in[21];
    const float* whh  = (const float*)d_in[22];
    const float* bih  = (const float*)d_in[23];
    const float* bhh  = (const float*)d_in[24];
    const float* clsw = (const float*)d_in[25];
    const float* clsb = (const float*)d_in[26];
    float* out = (float*)d_out;

    float *p_emb, *p_Q, *p_K, *p_attn, *p_An, *p_X1, *p_G1, *p_X2, *p_G2, *p_feat, *p_gemb, *p_gi;
    cudaGetSymbolAddress((void**)&p_emb,  d_emb);
    cudaGetSymbolAddress((void**)&p_Q,    d_Qm);
    cudaGetSymbolAddress((void**)&p_K,    d_Km);
    cudaGetSymbolAddress((void**)&p_attn, d_attn);
    cudaGetSymbolAddress((void**)&p_An,   d_An);
    cudaGetSymbolAddress((void**)&p_X1,   d_X1);
    cudaGetSymbolAddress((void**)&p_G1,   d_G1);
    cudaGetSymbolAddress((void**)&p_X2,   d_X2);
    cudaGetSymbolAddress((void**)&p_G2,   d_G2);
    cudaGetSymbolAddress((void**)&p_feat, d_feat);
    cudaGetSymbolAddress((void**)&p_gemb, d_gemb);
    cudaGetSymbolAddress((void**)&p_gi,   d_gi);

    k_init<<<1, 128>>>(out);
    k_cwtconv1<<<NWIN, 256>>>(tw, wavr, wavi, c1w, c1b);
    k_bn1fin<<<1, 16>>>(bn1g, bn1b);
    k_conv2<<<NWIN, 256>>>(c2w, c2b);
    k_bn2fin<<<1, 32>>>(bn2g, bn2b);
    k_feat<<<NWIN, 256>>>();

    k_gemm<0, true><<<dim3(2, 50, 1), 256>>>(p_feat, fcw, fcb, p_emb, 3200, 128, 32, 0, 0, 0, 1.f);
    k_gemm<0, true><<<dim3(2, 50, 1), 256>>>(p_emb, qw, qb, p_Q, 3200, 128, 128, 0, 0, 0, 1.f);
    k_gemm<0, true><<<dim3(2, 50, 1), 256>>>(p_emb, kw, kb, p_K, 3200, 128, 128, 0, 0, 0, 1.f);
    k_gemm<2, true><<<dim3(4, 4, 16), 256>>>(p_Q, p_K, nullptr, p_attn,
                                             200, 200, 128, 25600, 25600, 40000, 0.08838834764831845f);
    k_adj<<<3200, 256>>>();
    k_deg<<<16, 256>>>();
    k_An<<<2500, 256>>>();
    k_gemm<0, false><<<dim3(4, 50, 1), 256>>>(p_emb, g1w, nullptr, p_X1, 3200, 256, 128, 0, 0, 0, 1.f);
    k_gemm<1, false><<<dim3(4, 4, 16), 256>>>(p_An, p_X1, g1b, p_G1, 200, 256, 200, 40000, 51200, 51200, 1.f);
    k_gemm<0, false><<<dim3(4, 50, 1), 256>>>(p_G1, g2w, nullptr, p_X2, 3200, 256, 256, 0, 0, 0, 1.f);
    k_gemm<1, false><<<dim3(4, 4, 16), 256>>>(p_An, p_X2, g2b, p_G2, 200, 256, 200, 40000, 51200, 51200, 1.f);
    k_gemb<<<16, 256>>>();
    k_gemm<0, true><<<dim3(12, 1, 1), 256>>>(p_gemb, wih, bih, p_gi, 16, 768, 256, 0, 0, 0, 1.f);
    k_gru<<<1, 256>>>(whh, bhh, clsw, clsb, out);
    k_avgvar<<<157, 256>>>(out);
}